// round 1
// baseline (speedup 1.0000x reference)
#include <cuda_runtime.h>
#include <math.h>

#define D     256
#define N0    1500
#define N1    1200
#define CATC  600
#define W96   96
#define NPIX  (N0*W96)      /* 144000 */
#define HID   256
#define H2    128

/* ---------------- device scratch (static globals; no allocations) -------- */
__device__ float g_s0[D];
__device__ float g_acc0[D];
__device__ float g_accH[D];
__device__ float g_accL[D];
__device__ float g_t[W96];          /* hm[0..nHc) then lm[0..nLc)           */
__device__ float g_meanH;
__device__ float g_c1[HID*NPIX];    /* relu(conv1) : 147.5 MB               */
__device__ float g_sum1[HID];
__device__ float g_sq1[HID];
__device__ float g_sum2[H2];
__device__ float g_sq2[H2];
__device__ float g_W2p[D*H2];       /* folded W2, layout [c][o]             */
__device__ float g_b2p[H2];
__device__ float g_a2[H2];
__device__ float g_be2[H2];

__device__ __forceinline__ float sigm(float v) { return 1.f/(1.f+expf(-v)); }

/* ---------------- zero accumulators -------------------------------------- */
__global__ void k_zero() {
    int t = threadIdx.x;
    g_acc0[t]=0.f; g_accH[t]=0.f; g_accL[t]=0.f;
    g_sum1[t]=0.f; g_sq1[t]=0.f;
    if (t < H2) { g_sum2[t]=0.f; g_sq2[t]=0.f; }
}

/* ---------------- channel-mean accumulation (ECA stage 1) ---------------- */
/* blocks 0..49 : z0 rows ;  blocks 50..89 : z1 rows (H if row<600 else L)  */
__global__ void k_accum(const float* __restrict__ z0, const float* __restrict__ z1) {
    int b = blockIdx.x, c = threadIdx.x;
    float acc = 0.f;
    if (b < 50) {
        int r0 = b*30;
        #pragma unroll 6
        for (int i=0;i<30;i++) acc += z0[(r0+i)*D + c];
        atomicAdd(&g_acc0[c], acc);
    } else {
        int r0 = (b-50)*30;
        #pragma unroll 6
        for (int i=0;i<30;i++) acc += z1[(r0+i)*D + c];
        if (r0 < CATC) atomicAdd(&g_accH[c], acc);
        else           atomicAdd(&g_accL[c], acc);
    }
}

/* ---------------- small prep: s0, hm, lm, meanH (single block) ----------- */
__global__ void k_prep(const float* __restrict__ z1,
                       const float* __restrict__ w1, const float* __restrict__ w2,
                       const float* __restrict__ w3, const float* __restrict__ w4,
                       const float* __restrict__ w5,
                       const int* __restrict__ cdrH, const int* __restrict__ cdrL,
                       const int* __restrict__ notH, const int* __restrict__ notL,
                       int nHc, int nLc, int nHn, int nLn) {
    __shared__ float y0[D];
    __shared__ float av[W96];
    __shared__ float bv[CATC];
    __shared__ float red[256];
    int t = threadIdx.x;

    /* s0 : sigmoid(conv5(mean_n z0)) */
    y0[t] = g_acc0[t] * (1.f/N0);
    __syncthreads();
    {
        float a = 0.f;
        #pragma unroll
        for (int k=0;k<5;k++) { int cc=t+k-2; if (cc>=0 && cc<D) a += w1[k]*y0[cc]; }
        g_s0[t] = sigm(a);
    }

    /* ---- H side ---- */
    float sH0;
    {
        float yh0=g_accH[0]*(1.f/CATC), yh1=g_accH[1]*(1.f/CATC), yh2=g_accH[2]*(1.f/CATC);
        sH0 = sigm(w2[2]*yh0 + w2[3]*yh1 + w2[4]*yh2);
    }
    if (t < nHc) av[t] = z1[cdrH[t]*D] * sH0;
    for (int j=t; j<nHn; j+=256) bv[j] = z1[notH[j]*D] * sH0;
    __syncthreads();
    float msumH = 0.f;
    if (t < nHc) { float ai=av[t]; for (int j=0;j<nHn;j++) msumH += fabsf(ai - bv[j]); }
    red[t] = (t<nHc)? msumH : 0.f;
    __syncthreads();
    for (int m=128;m>0;m>>=1){ if(t<m) red[t]+=red[t+m]; __syncthreads(); }
    float gH = sigm(w4[2] * red[0] / ((float)nHc*(float)nHn));
    float myhm = (t<nHc) ? gH * msumH / (float)nHn : 0.f;
    if (t < nHc) g_t[t] = myhm;
    __syncthreads();

    /* ---- L side ---- */
    float sL0;
    {
        float yl0=g_accL[0]*(1.f/CATC), yl1=g_accL[1]*(1.f/CATC), yl2=g_accL[2]*(1.f/CATC);
        sL0 = sigm(w3[2]*yl0 + w3[3]*yl1 + w3[4]*yl2);
    }
    if (t < nLc) av[t] = z1[(CATC+cdrL[t])*D] * sL0;
    for (int j=t; j<nLn; j+=256) bv[j] = z1[(CATC+notL[j])*D] * sL0;
    __syncthreads();
    float msumL = 0.f;
    if (t < nLc) { float ai=av[t]; for (int j=0;j<nLn;j++) msumL += fabsf(ai - bv[j]); }
    red[t] = (t<nLc)? msumL : 0.f;
    __syncthreads();
    for (int m=128;m>0;m>>=1){ if(t<m) red[t]+=red[t+m]; __syncthreads(); }
    float gL = sigm(w5[2] * red[0] / ((float)nLc*(float)nLn));
    if (t < nLc) g_t[nHc + t] = gL * msumL / (float)nLn;
    __syncthreads();

    /* meanH */
    red[t] = myhm;
    __syncthreads();
    for (int m=128;m>0;m>>=1){ if(t<m) red[t]+=red[t+m]; __syncthreads(); }
    if (t==0) g_meanH = red[0] / (float)nHc;
}

/* ---------------- GEMM1 fused with z_cat generation + bias + relu -------- */
/* block = (o-tile 128 , one h).  out tile 128x96, thread tile 8x6.         */
__global__ __launch_bounds__(256) void k_gemm1(const float* __restrict__ z0,
                                               const float* __restrict__ W1,
                                               const float* __restrict__ b1,
                                               int nHc) {
    const int h     = blockIdx.y;
    const int obase = blockIdx.x * 128;
    const int tid   = threadIdx.x;
    const int to    = tid >> 4;   /* 0..15 -> 8 outputs each */
    const int tw    = tid & 15;   /* 0..15 -> 6 pixels each  */

    __shared__ float xs[D], m0s[D], m1s[D], tts[W96];
    __shared__ float As[32*132];
    __shared__ float Bs[32*100];

    if (tid < W96) tts[tid] = g_t[tid];
    float xv = z0[h*D + tid] * g_s0[tid];
    xs[tid] = xv;
    __syncthreads();
    {
        float s = 0.f;
        for (int k=0;k<nHc;k++) s += fabsf(xv - tts[k]);
        m0s[tid] = s / (float)nHc;
        m1s[tid] = xv * g_meanH;
    }
    __syncthreads();

    float acc[8][6];
    #pragma unroll
    for (int i=0;i<8;i++)
        #pragma unroll
        for (int j=0;j<6;j++) acc[i][j]=0.f;

    for (int kc = 0; kc < 512; kc += 32) {
        /* stage B : build z_cat chunk on the fly */
        #pragma unroll
        for (int r=0;r<12;r++) {
            int v  = tid + r*256;
            int ci = v / 96, w = v - ci*96;
            int c  = kc + ci;
            float tval = tts[w];
            float val;
            if (c < 256) {
                float src = (w < nHc) ? xs[c] : m0s[c];
                val = fabsf(src - tval);
            } else {
                int cc = c - 256;
                val = (w < nHc) ? xs[cc]*tval : fabsf(m1s[cc] - tval);
            }
            Bs[ci*100 + w] = val;
        }
        /* stage A : W1 chunk (transposed into [ci][o]) */
        #pragma unroll
        for (int r=0;r<16;r++) {
            int v  = tid + r*256;
            int ci = v & 31, o = v >> 5;
            As[ci*132 + o] = W1[(obase + o)*512 + kc + ci];
        }
        __syncthreads();
        #pragma unroll
        for (int ci=0;ci<32;ci++) {
            float4 a0 = *(const float4*)&As[ci*132 + 8*to];
            float4 a1 = *(const float4*)&As[ci*132 + 8*to + 4];
            float bvl[6];
            #pragma unroll
            for (int j=0;j<6;j++) bvl[j] = Bs[ci*100 + 6*tw + j];
            float avr[8] = {a0.x,a0.y,a0.z,a0.w,a1.x,a1.y,a1.z,a1.w};
            #pragma unroll
            for (int i=0;i<8;i++)
                #pragma unroll
                for (int j=0;j<6;j++)
                    acc[i][j] = fmaf(avr[i], bvl[j], acc[i][j]);
        }
        __syncthreads();
    }

    const int pbase = h*W96 + 6*tw;
    #pragma unroll
    for (int i=0;i<8;i++) {
        int o = obase + 8*to + i;
        float bias = b1[o];
        #pragma unroll
        for (int j=0;j<6;j++) {
            float rr = fmaxf(acc[i][j] + bias, 0.f);
            g_c1[o*NPIX + pbase + j] = rr;
        }
    }
}

/* ---------------- per-channel stats over g_c1 ---------------------------- */
__global__ void k_stats1() {
    const int c = blockIdx.x, chunk = blockIdx.y, t = threadIdx.x;
    const float* p = g_c1 + c*NPIX;
    int start = chunk*18000, end = start + 18000;
    float s=0.f, q=0.f;
    for (int i=start+t; i<end; i+=256) { float v=p[i]; s+=v; q+=v*v; }
    __shared__ float rs[256], rq[256];
    rs[t]=s; rq[t]=q; __syncthreads();
    for (int m=128;m>0;m>>=1){ if(t<m){rs[t]+=rs[t+m]; rq[t]+=rq[t+m];} __syncthreads(); }
    if (t==0){ atomicAdd(&g_sum1[c], rs[0]); atomicAdd(&g_sq1[c], rq[0]); }
}

/* ---------------- fold BN1 affine into W2 -------------------------------- */
__global__ void k_fold(const float* __restrict__ W2, const float* __restrict__ b2,
                       const float* __restrict__ g1, const float* __restrict__ bb1) {
    __shared__ float al[D], be[D];
    int t = threadIdx.x;
    float mean = g_sum1[t] * (1.f/NPIX);
    float var  = g_sq1[t]  * (1.f/NPIX) - mean*mean;
    float a    = g1[t] * rsqrtf(var + 1e-5f);
    al[t] = a; be[t] = bb1[t] - mean*a;
    __syncthreads();
    for (int v=t; v<H2*D; v+=256) {
        int o = v >> 8, c = v & 255;
        g_W2p[c*H2 + o] = W2[v] * al[c];
    }
    if (t < H2) {
        float s = b2[t];
        for (int c=0;c<D;c++) s += W2[t*D + c] * be[c];
        g_b2p[t] = s;
    }
}

/* ---------------- GEMM2 (+bias+relu) ------------------------------------- */
__global__ __launch_bounds__(256) void k_gemm2(float* __restrict__ out) {
    const int h   = blockIdx.x;
    const int tid = threadIdx.x;
    const int to  = tid >> 4, tw = tid & 15;
    __shared__ float As[32*132];
    __shared__ float Bs[32*100];
    float acc[8][6];
    #pragma unroll
    for (int i=0;i<8;i++)
        #pragma unroll
        for (int j=0;j<6;j++) acc[i][j]=0.f;

    for (int kc=0; kc<256; kc+=32) {
        #pragma unroll
        for (int r=0;r<12;r++) {
            int v = tid + r*256;
            int ci = v / 96, w = v - ci*96;
            Bs[ci*100 + w] = g_c1[(kc+ci)*NPIX + h*W96 + w];
        }
        #pragma unroll
        for (int r=0;r<16;r++) {
            int v = tid + r*256;
            int ci = v >> 7, o = v & 127;
            As[ci*132 + o] = g_W2p[(kc+ci)*H2 + o];
        }
        __syncthreads();
        #pragma unroll
        for (int ci=0;ci<32;ci++) {
            float4 a0 = *(const float4*)&As[ci*132 + 8*to];
            float4 a1 = *(const float4*)&As[ci*132 + 8*to + 4];
            float bvl[6];
            #pragma unroll
            for (int j=0;j<6;j++) bvl[j] = Bs[ci*100 + 6*tw + j];
            float avr[8] = {a0.x,a0.y,a0.z,a0.w,a1.x,a1.y,a1.z,a1.w};
            #pragma unroll
            for (int i=0;i<8;i++)
                #pragma unroll
                for (int j=0;j<6;j++)
                    acc[i][j] = fmaf(avr[i], bvl[j], acc[i][j]);
        }
        __syncthreads();
    }
    const int pbase = h*W96 + 6*tw;
    #pragma unroll
    for (int i=0;i<8;i++) {
        int o = 8*to + i;
        float bias = g_b2p[o];
        #pragma unroll
        for (int j=0;j<6;j++) {
            float rr = fmaxf(acc[i][j] + bias, 0.f);
            out[o*NPIX + pbase + j] = rr;
        }
    }
}

/* ---------------- stats over relu(c2) (stored in out) -------------------- */
__global__ void k_stats2(const float* __restrict__ out) {
    const int c = blockIdx.x, chunk = blockIdx.y, t = threadIdx.x;
    const float* p = out + c*NPIX;
    int start = chunk*18000, end = start + 18000;
    float s=0.f, q=0.f;
    for (int i=start+t; i<end; i+=256) { float v=p[i]; s+=v; q+=v*v; }
    __shared__ float rs[256], rq[256];
    rs[t]=s; rq[t]=q; __syncthreads();
    for (int m=128;m>0;m>>=1){ if(t<m){rs[t]+=rs[t+m]; rq[t]+=rq[t+m];} __syncthreads(); }
    if (t==0){ atomicAdd(&g_sum2[c], rs[0]); atomicAdd(&g_sq2[c], rq[0]); }
}

__global__ void k_ab2(const float* __restrict__ g2, const float* __restrict__ bb2) {
    int t = threadIdx.x;           /* 128 threads */
    float mean = g_sum2[t]*(1.f/NPIX);
    float var  = g_sq2[t]*(1.f/NPIX) - mean*mean;
    float a    = g2[t]*rsqrtf(var + 1e-5f);
    g_a2[t] = a; g_be2[t] = bb2[t] - mean*a;
}

/* ---------------- final BN2 affine in place ------------------------------ */
__global__ void k_final(float* __restrict__ out) {
    size_t idx = (size_t)blockIdx.x*256 + threadIdx.x;
    size_t i4  = idx * 4;
    int c = (int)(i4 / NPIX);
    float a = g_a2[c], b = g_be2[c];
    float4 v = *(float4*)(out + i4);
    v.x = fmaf(a, v.x, b); v.y = fmaf(a, v.y, b);
    v.z = fmaf(a, v.z, b); v.w = fmaf(a, v.w, b);
    *(float4*)(out + i4) = v;
}

/* ---------------- launch ------------------------------------------------- */
extern "C" void kernel_launch(void* const* d_in, const int* in_sizes, int n_in,
                              void* d_out, int out_size) {
    const float* z0  = (const float*)d_in[0];
    const float* z1  = (const float*)d_in[1];
    const float* w1  = (const float*)d_in[2];
    const float* w2  = (const float*)d_in[3];
    const float* w3  = (const float*)d_in[4];
    const float* w4  = (const float*)d_in[5];
    const float* w5  = (const float*)d_in[6];
    const float* W1  = (const float*)d_in[7];
    const float* b1  = (const float*)d_in[8];
    const float* g1  = (const float*)d_in[9];
    const float* bb1 = (const float*)d_in[10];
    const float* W2  = (const float*)d_in[11];
    const float* b2  = (const float*)d_in[12];
    const float* g2  = (const float*)d_in[13];
    const float* bb2 = (const float*)d_in[14];
    /* d_in[15] = catsite (fixed 600, unused) */
    const int* cdrH = (const int*)d_in[16];
    const int* cdrL = (const int*)d_in[17];
    const int* notH = (const int*)d_in[18];
    const int* notL = (const int*)d_in[19];
    int nHc = in_sizes[16], nLc = in_sizes[17];
    int nHn = in_sizes[18], nLn = in_sizes[19];
    float* out = (float*)d_out;

    k_zero  <<<1, 256>>>();
    k_accum <<<90, 256>>>(z0, z1);
    k_prep  <<<1, 256>>>(z1, w1, w2, w3, w4, w5, cdrH, cdrL, notH, notL,
                         nHc, nLc, nHn, nLn);
    k_gemm1 <<<dim3(2, N0), 256>>>(z0, W1, b1, nHc);
    k_stats1<<<dim3(HID, 8), 256>>>();
    k_fold  <<<1, 256>>>(W2, b2, g1, bb1);
    k_gemm2 <<<N0, 256>>>(out);
    k_stats2<<<dim3(H2, 8), 256>>>(out);
    k_ab2   <<<1, 128>>>(g2, bb2);
    k_final <<<18000, 256>>>(out);
}

// round 2
// speedup vs baseline: 1.1455x; 1.1455x over previous
#include <cuda_runtime.h>
#include <math.h>

#define D     256
#define N0    1500
#define N1    1200
#define CATC  600
#define W96   96
#define NPIX  (N0*W96)      /* 144000 */
#define HID   256
#define H2    128
#define NT    48            /* column tile for gemm1 */

/* ---------------- device scratch (static globals; no allocations) -------- */
__device__ float g_s0[D];
__device__ float g_acc0[D];
__device__ float g_accH[D];
__device__ float g_accL[D];
__device__ float g_t[W96];          /* hm[0..nHc) then lm[0..nLc)           */
__device__ float g_meanH;
__device__ float g_W1t[512*256];    /* W1 transposed [k][o]                 */
__device__ float g_x [N0*D];        /* per-h scaled z0                      */
__device__ float g_m0[N0*D];
__device__ float g_m1[N0*D];
__device__ float g_u [N0*D];        /* u[h][o]                              */
__device__ float g_c1[HID*NPIX];    /* relu(conv1) : 147.5 MB               */
__device__ float g_sum1[HID];
__device__ float g_sq1[HID];
__device__ float g_sum2[H2];
__device__ float g_sq2[H2];
__device__ float g_W2p[D*H2];       /* folded W2, layout [c][o]             */
__device__ float g_b2p[H2];
__device__ float g_a2[H2];
__device__ float g_be2[H2];

__device__ __forceinline__ float sigm(float v) { return 1.f/(1.f+expf(-v)); }

/* ---------------- zero accumulators -------------------------------------- */
__global__ void k_zero() {
    int t = threadIdx.x;
    g_acc0[t]=0.f; g_accH[t]=0.f; g_accL[t]=0.f;
    g_sum1[t]=0.f; g_sq1[t]=0.f;
    if (t < H2) { g_sum2[t]=0.f; g_sq2[t]=0.f; }
}

/* ---------------- transpose W1 -> [k][o] --------------------------------- */
__global__ void k_tr(const float* __restrict__ W1) {
    int c = blockIdx.x, o = threadIdx.x;
    g_W1t[c*256 + o] = W1[o*512 + c];
}

/* ---------------- channel-mean accumulation (ECA stage 1) ---------------- */
__global__ void k_accum(const float* __restrict__ z0, const float* __restrict__ z1) {
    int b = blockIdx.x, c = threadIdx.x;
    float acc = 0.f;
    if (b < 50) {
        int r0 = b*30;
        #pragma unroll 6
        for (int i=0;i<30;i++) acc += z0[(r0+i)*D + c];
        atomicAdd(&g_acc0[c], acc);
    } else {
        int r0 = (b-50)*30;
        #pragma unroll 6
        for (int i=0;i<30;i++) acc += z1[(r0+i)*D + c];
        if (r0 < CATC) atomicAdd(&g_accH[c], acc);
        else           atomicAdd(&g_accL[c], acc);
    }
}

/* ---------------- small prep: s0, hm, lm, meanH (single block) ----------- */
__global__ void k_prep(const float* __restrict__ z1,
                       const float* __restrict__ w1, const float* __restrict__ w2,
                       const float* __restrict__ w3, const float* __restrict__ w4,
                       const float* __restrict__ w5,
                       const int* __restrict__ cdrH, const int* __restrict__ cdrL,
                       const int* __restrict__ notH, const int* __restrict__ notL,
                       int nHc, int nLc, int nHn, int nLn) {
    __shared__ float y0[D];
    __shared__ float av[W96];
    __shared__ float bv[CATC];
    __shared__ float red[256];
    int t = threadIdx.x;

    y0[t] = g_acc0[t] * (1.f/N0);
    __syncthreads();
    {
        float a = 0.f;
        #pragma unroll
        for (int k=0;k<5;k++) { int cc=t+k-2; if (cc>=0 && cc<D) a += w1[k]*y0[cc]; }
        g_s0[t] = sigm(a);
    }

    float sH0;
    {
        float yh0=g_accH[0]*(1.f/CATC), yh1=g_accH[1]*(1.f/CATC), yh2=g_accH[2]*(1.f/CATC);
        sH0 = sigm(w2[2]*yh0 + w2[3]*yh1 + w2[4]*yh2);
    }
    if (t < nHc) av[t] = z1[cdrH[t]*D] * sH0;
    for (int j=t; j<nHn; j+=256) bv[j] = z1[notH[j]*D] * sH0;
    __syncthreads();
    float msumH = 0.f;
    if (t < nHc) { float ai=av[t]; for (int j=0;j<nHn;j++) msumH += fabsf(ai - bv[j]); }
    red[t] = (t<nHc)? msumH : 0.f;
    __syncthreads();
    for (int m=128;m>0;m>>=1){ if(t<m) red[t]+=red[t+m]; __syncthreads(); }
    float gH = sigm(w4[2] * red[0] / ((float)nHc*(float)nHn));
    float myhm = (t<nHc) ? gH * msumH / (float)nHn : 0.f;
    if (t < nHc) g_t[t] = myhm;
    __syncthreads();

    float sL0;
    {
        float yl0=g_accL[0]*(1.f/CATC), yl1=g_accL[1]*(1.f/CATC), yl2=g_accL[2]*(1.f/CATC);
        sL0 = sigm(w3[2]*yl0 + w3[3]*yl1 + w3[4]*yl2);
    }
    if (t < nLc) av[t] = z1[(CATC+cdrL[t])*D] * sL0;
    for (int j=t; j<nLn; j+=256) bv[j] = z1[(CATC+notL[j])*D] * sL0;
    __syncthreads();
    float msumL = 0.f;
    if (t < nLc) { float ai=av[t]; for (int j=0;j<nLn;j++) msumL += fabsf(ai - bv[j]); }
    red[t] = (t<nLc)? msumL : 0.f;
    __syncthreads();
    for (int m=128;m>0;m>>=1){ if(t<m) red[t]+=red[t+m]; __syncthreads(); }
    float gL = sigm(w5[2] * red[0] / ((float)nLc*(float)nLn));
    if (t < nLc) g_t[nHc + t] = gL * msumL / (float)nLn;
    __syncthreads();

    red[t] = myhm;
    __syncthreads();
    for (int m=128;m>0;m>>=1){ if(t<m) red[t]+=red[t+m]; __syncthreads(); }
    if (t==0) g_meanH = red[0] / (float)nHc;
}

/* ---------------- per-h vectors x, m0, m1 and u = W1hi . x --------------- */
#define HB 10
__global__ __launch_bounds__(256) void k_pre2(const float* __restrict__ z0, int nHc) {
    __shared__ float xsall[HB][D];
    __shared__ float ts[W96];
    const int t = threadIdx.x;
    const int hbase = blockIdx.x * HB;
    if (t < W96) ts[t] = g_t[t];
    const float s0 = g_s0[t];
    const float mh = g_meanH;
    const float inv = 1.f / (float)nHc;
    __syncthreads();
    #pragma unroll
    for (int hh=0; hh<HB; hh++) {
        int h = hbase + hh;
        float x = z0[h*D + t] * s0;
        xsall[hh][t] = x;
        g_x [h*D + t] = x;
        float s = 0.f;
        for (int k=0;k<nHc;k++) s += fabsf(x - ts[k]);
        g_m0[h*D + t] = s * inv;
        g_m1[h*D + t] = x * mh;
    }
    __syncthreads();
    /* u[o] for all HB h's : thread = o */
    float u[HB];
    #pragma unroll
    for (int hh=0;hh<HB;hh++) u[hh]=0.f;
    for (int c=0;c<D;c++) {
        float wv = g_W1t[(256+c)*256 + t];
        #pragma unroll
        for (int hh=0;hh<HB;hh++) u[hh] = fmaf(wv, xsall[hh][c], u[hh]);
    }
    #pragma unroll
    for (int hh=0;hh<HB;hh++) g_u[(hbase+hh)*D + t] = u[hh];
}

/* ---------------- GEMM1-H : K=256, cols w<nHc, +u*hm rank-1 -------------- */
__global__ __launch_bounds__(256,2) void k_g1a(const float* __restrict__ b1, int nHc) {
    const int h   = blockIdx.y;
    const int wb  = blockIdx.x * NT;
    const int tid = threadIdx.x;
    const int tw  = tid & 7;      /* 6 cols each  */
    const int to  = tid >> 3;     /* 8 outs each  */

    __shared__ float xs[D];
    __shared__ float ts[NT];
    __shared__ float As[32*256];
    __shared__ float Bs[32*NT];

    xs[tid] = g_x[h*D + tid];
    if (tid < NT) { int w = wb + tid; ts[tid] = (w < nHc) ? g_t[w] : 0.f; }
    __syncthreads();

    float acc[8][6];
    #pragma unroll
    for (int i=0;i<8;i++)
        #pragma unroll
        for (int j=0;j<6;j++) acc[i][j]=0.f;

    for (int kc=0; kc<256; kc+=32) {
        #pragma unroll
        for (int r=0;r<8;r++) {
            int i4 = tid + r*256;         /* float4 id, 2048 total */
            int ci = i4 >> 6, col = (i4 & 63) << 2;
            *(float4*)&As[ci*256 + col] = *(const float4*)&g_W1t[(kc+ci)*256 + col];
        }
        #pragma unroll
        for (int r=0;r<6;r++) {
            int v = tid + r*256;          /* 1536 total */
            int ci = v / NT, w = v - ci*NT;
            Bs[ci*NT + w] = fabsf(xs[kc+ci] - ts[w]);
        }
        __syncthreads();
        #pragma unroll
        for (int ci=0;ci<32;ci++) {
            float4 a0 = *(const float4*)&As[ci*256 + to*8];
            float4 a1 = *(const float4*)&As[ci*256 + to*8 + 4];
            float2 b0 = *(const float2*)&Bs[ci*NT + tw*6];
            float2 b1v= *(const float2*)&Bs[ci*NT + tw*6 + 2];
            float2 b2 = *(const float2*)&Bs[ci*NT + tw*6 + 4];
            float av[8] = {a0.x,a0.y,a0.z,a0.w,a1.x,a1.y,a1.z,a1.w};
            float bv[6] = {b0.x,b0.y,b1v.x,b1v.y,b2.x,b2.y};
            #pragma unroll
            for (int i=0;i<8;i++)
                #pragma unroll
                for (int j=0;j<6;j++)
                    acc[i][j] = fmaf(av[i], bv[j], acc[i][j]);
        }
        __syncthreads();
    }

    /* epilogue : + u*hm + bias, relu, store, stats */
    float uo[8];
    #pragma unroll
    for (int i=0;i<8;i++) uo[i] = g_u[h*D + to*8 + i];
    #pragma unroll
    for (int i=0;i<8;i++) {
        int o = to*8 + i;
        float bias = b1[o];
        float s = 0.f, q = 0.f;
        #pragma unroll
        for (int j=0;j<6;j++) {
            int w = wb + tw*6 + j;
            float r = fmaxf(fmaf(uo[i], ts[tw*6+j], acc[i][j]) + bias, 0.f);
            if (w < nHc) {
                g_c1[(size_t)o*NPIX + h*W96 + w] = r;
                s += r; q += r*r;
            }
        }
        #pragma unroll
        for (int off=4; off; off>>=1) {
            s += __shfl_down_sync(0xffffffffu, s, off, 8);
            q += __shfl_down_sync(0xffffffffu, q, off, 8);
        }
        if (tw == 0) { atomicAdd(&g_sum1[o], s); atomicAdd(&g_sq1[o], q); }
    }
}

/* ---------------- GEMM1-L : K=512 over (m0|m1), cols nHc..95 ------------- */
__global__ __launch_bounds__(256,2) void k_g1b(const float* __restrict__ b1,
                                               int nHc, int nLc) {
    const int h   = blockIdx.y;
    const int wb  = blockIdx.x * NT;
    const int tid = threadIdx.x;
    const int tw  = tid & 7;
    const int to  = tid >> 3;

    __shared__ float m0s[D], m1s[D];
    __shared__ float ts[NT];
    __shared__ float As[32*256];
    __shared__ float Bs[32*NT];

    m0s[tid] = g_m0[h*D + tid];
    m1s[tid] = g_m1[h*D + tid];
    if (tid < NT) { int w = wb + tid; ts[tid] = (w < nLc) ? g_t[nHc + w] : 0.f; }
    __syncthreads();

    float acc[8][6];
    #pragma unroll
    for (int i=0;i<8;i++)
        #pragma unroll
        for (int j=0;j<6;j++) acc[i][j]=0.f;

    for (int kc=0; kc<512; kc+=32) {
        const float* src = (kc < 256) ? (m0s + kc) : (m1s + kc - 256);
        #pragma unroll
        for (int r=0;r<8;r++) {
            int i4 = tid + r*256;
            int ci = i4 >> 6, col = (i4 & 63) << 2;
            *(float4*)&As[ci*256 + col] = *(const float4*)&g_W1t[(kc+ci)*256 + col];
        }
        #pragma unroll
        for (int r=0;r<6;r++) {
            int v = tid + r*256;
            int ci = v / NT, w = v - ci*NT;
            Bs[ci*NT + w] = fabsf(src[ci] - ts[w]);
        }
        __syncthreads();
        #pragma unroll
        for (int ci=0;ci<32;ci++) {
            float4 a0 = *(const float4*)&As[ci*256 + to*8];
            float4 a1 = *(const float4*)&As[ci*256 + to*8 + 4];
            float2 b0 = *(const float2*)&Bs[ci*NT + tw*6];
            float2 b1v= *(const float2*)&Bs[ci*NT + tw*6 + 2];
            float2 b2 = *(const float2*)&Bs[ci*NT + tw*6 + 4];
            float av[8] = {a0.x,a0.y,a0.z,a0.w,a1.x,a1.y,a1.z,a1.w};
            float bv[6] = {b0.x,b0.y,b1v.x,b1v.y,b2.x,b2.y};
            #pragma unroll
            for (int i=0;i<8;i++)
                #pragma unroll
                for (int j=0;j<6;j++)
                    acc[i][j] = fmaf(av[i], bv[j], acc[i][j]);
        }
        __syncthreads();
    }

    #pragma unroll
    for (int i=0;i<8;i++) {
        int o = to*8 + i;
        float bias = b1[o];
        float s = 0.f, q = 0.f;
        #pragma unroll
        for (int j=0;j<6;j++) {
            int w = wb + tw*6 + j;
            float r = fmaxf(acc[i][j] + bias, 0.f);
            if (w < nLc) {
                g_c1[(size_t)o*NPIX + h*W96 + nHc + w] = r;
                s += r; q += r*r;
            }
        }
        #pragma unroll
        for (int off=4; off; off>>=1) {
            s += __shfl_down_sync(0xffffffffu, s, off, 8);
            q += __shfl_down_sync(0xffffffffu, q, off, 8);
        }
        if (tw == 0) { atomicAdd(&g_sum1[o], s); atomicAdd(&g_sq1[o], q); }
    }
}

/* ---------------- fold BN1 affine into W2 -------------------------------- */
__global__ void k_fold(const float* __restrict__ W2, const float* __restrict__ b2,
                       const float* __restrict__ g1, const float* __restrict__ bb1) {
    __shared__ float al[D], be[D];
    int t = threadIdx.x;
    float mean = g_sum1[t] * (1.f/NPIX);
    float var  = g_sq1[t]  * (1.f/NPIX) - mean*mean;
    float a    = g1[t] * rsqrtf(var + 1e-5f);
    al[t] = a; be[t] = bb1[t] - mean*a;
    __syncthreads();
    for (int v=t; v<H2*D; v+=256) {
        int o = v >> 8, c = v & 255;
        g_W2p[c*H2 + o] = W2[v] * al[c];
    }
    if (t < H2) {
        float s = b2[t];
        for (int c=0;c<D;c++) s += W2[t*D + c] * be[c];
        g_b2p[t] = s;
    }
}

/* ---------------- GEMM2 : M=128, K=256, N=144000, fused stats ------------ */
__global__ __launch_bounds__(256,2) void k_gemm2(float* __restrict__ out) {
    const int pb  = blockIdx.x * 128;
    const int tid = threadIdx.x;
    const int tp  = tid & 15;     /* 8 pixels each */
    const int to  = tid >> 4;     /* 8 outs each   */

    __shared__ float As[32*128];
    __shared__ float Bs[32*128];

    float acc[8][8];
    #pragma unroll
    for (int i=0;i<8;i++)
        #pragma unroll
        for (int j=0;j<8;j++) acc[i][j]=0.f;

    for (int kc=0; kc<256; kc+=32) {
        #pragma unroll
        for (int r=0;r<4;r++) {
            int i4 = tid + r*256;          /* 1024 float4 */
            int ci = i4 >> 5, col = (i4 & 31) << 2;
            *(float4*)&As[ci*128 + col] = *(const float4*)&g_W2p[(kc+ci)*H2 + col];
        }
        #pragma unroll
        for (int r=0;r<4;r++) {
            int i4 = tid + r*256;
            int ci = i4 >> 5, col = (i4 & 31) << 2;
            *(float4*)&Bs[ci*128 + col] = *(const float4*)&g_c1[(size_t)(kc+ci)*NPIX + pb + col];
        }
        __syncthreads();
        #pragma unroll
        for (int ci=0;ci<32;ci++) {
            float4 a0 = *(const float4*)&As[ci*128 + to*8];
            float4 a1 = *(const float4*)&As[ci*128 + to*8 + 4];
            float4 c0 = *(const float4*)&Bs[ci*128 + tp*8];
            float4 c1 = *(const float4*)&Bs[ci*128 + tp*8 + 4];
            float av[8] = {a0.x,a0.y,a0.z,a0.w,a1.x,a1.y,a1.z,a1.w};
            float bv[8] = {c0.x,c0.y,c0.z,c0.w,c1.x,c1.y,c1.z,c1.w};
            #pragma unroll
            for (int i=0;i<8;i++)
                #pragma unroll
                for (int j=0;j<8;j++)
                    acc[i][j] = fmaf(av[i], bv[j], acc[i][j]);
        }
        __syncthreads();
    }

    #pragma unroll
    for (int i=0;i<8;i++) {
        int o = to*8 + i;
        float bias = g_b2p[o];
        float s = 0.f, q = 0.f;
        #pragma unroll
        for (int j=0;j<8;j++) {
            float r = fmaxf(acc[i][j] + bias, 0.f);
            out[(size_t)o*NPIX + pb + tp*8 + j] = r;
            s += r; q += r*r;
        }
        #pragma unroll
        for (int off=8; off; off>>=1) {
            s += __shfl_down_sync(0xffffffffu, s, off, 16);
            q += __shfl_down_sync(0xffffffffu, q, off, 16);
        }
        if (tp == 0) { atomicAdd(&g_sum2[o], s); atomicAdd(&g_sq2[o], q); }
    }
}

__global__ void k_ab2(const float* __restrict__ g2, const float* __restrict__ bb2) {
    int t = threadIdx.x;           /* 128 threads */
    float mean = g_sum2[t]*(1.f/NPIX);
    float var  = g_sq2[t]*(1.f/NPIX) - mean*mean;
    float a    = g2[t]*rsqrtf(var + 1e-5f);
    g_a2[t] = a; g_be2[t] = bb2[t] - mean*a;
}

/* ---------------- final BN2 affine in place ------------------------------ */
__global__ void k_final(float* __restrict__ out) {
    size_t idx = (size_t)blockIdx.x*256 + threadIdx.x;
    size_t i4  = idx * 4;
    int c = (int)(i4 / NPIX);
    float a = g_a2[c], b = g_be2[c];
    float4 v = *(float4*)(out + i4);
    v.x = fmaf(a, v.x, b); v.y = fmaf(a, v.y, b);
    v.z = fmaf(a, v.z, b); v.w = fmaf(a, v.w, b);
    *(float4*)(out + i4) = v;
}

/* ---------------- launch ------------------------------------------------- */
extern "C" void kernel_launch(void* const* d_in, const int* in_sizes, int n_in,
                              void* d_out, int out_size) {
    const float* z0  = (const float*)d_in[0];
    const float* z1  = (const float*)d_in[1];
    const float* w1  = (const float*)d_in[2];
    const float* w2  = (const float*)d_in[3];
    const float* w3  = (const float*)d_in[4];
    const float* w4  = (const float*)d_in[5];
    const float* w5  = (const float*)d_in[6];
    const float* W1  = (const float*)d_in[7];
    const float* b1  = (const float*)d_in[8];
    const float* g1  = (const float*)d_in[9];
    const float* bb1 = (const float*)d_in[10];
    const float* W2  = (const float*)d_in[11];
    const float* b2  = (const float*)d_in[12];
    const float* g2  = (const float*)d_in[13];
    const float* bb2 = (const float*)d_in[14];
    const int* cdrH = (const int*)d_in[16];
    const int* cdrL = (const int*)d_in[17];
    const int* notH = (const int*)d_in[18];
    const int* notL = (const int*)d_in[19];
    int nHc = in_sizes[16], nLc = in_sizes[17];
    int nHn = in_sizes[18], nLn = in_sizes[19];
    float* out = (float*)d_out;

    k_zero  <<<1, 256>>>();
    k_tr    <<<512, 256>>>(W1);
    k_accum <<<90, 256>>>(z0, z1);
    k_prep  <<<1, 256>>>(z1, w1, w2, w3, w4, w5, cdrH, cdrL, notH, notL,
                         nHc, nLc, nHn, nLn);
    k_pre2  <<<N0/HB, 256>>>(z0, nHc);
    int tH = (nHc + NT - 1) / NT;
    int tL = (nLc + NT - 1) / NT;
    if (tH > 0) k_g1a <<<dim3(tH, N0), 256>>>(b1, nHc);
    if (tL > 0) k_g1b <<<dim3(tL, N0), 256>>>(b1, nHc, nLc);
    k_fold  <<<1, 256>>>(W2, b2, g1, bb1);
    k_gemm2 <<<NPIX/128, 256>>>(out);
    k_ab2   <<<1, 128>>>(g2, bb2);
    k_final <<<18000, 256>>>(out);
}

// round 3
// speedup vs baseline: 1.2062x; 1.0531x over previous
#include <cuda_runtime.h>
#include <math.h>

#define D     256
#define N0    1500
#define N1    1200
#define CATC  600
#define W96   96
#define NPIX  (N0*W96)      /* 144000 */
#define HID   256
#define H2    128

/* ---------------- device scratch (static globals; no allocations) -------- */
__device__ float g_s0[D];
__device__ float g_acc0[D];
__device__ float g_accH[D];
__device__ float g_accL[D];
__device__ float g_t[W96];          /* hm[0..nHc) then lm[0..nLc)           */
__device__ float g_meanH;
__device__ float g_W1t[512*256];    /* W1 transposed [k][o]                 */
__device__ float g_x [N0*D];        /* per-h scaled z0                      */
__device__ float g_m0[N0*D];
__device__ float g_m1[N0*D];
__device__ float g_u [N0*D];        /* u[h][o]  rank-1 part                 */
__device__ float g_c1[HID*NPIX];    /* relu(conv1) : 147.5 MB               */
__device__ float g_sum1[HID];
__device__ float g_sq1[HID];
__device__ float g_sum2[H2];
__device__ float g_sq2[H2];
__device__ float g_W2p[D*H2];       /* folded W2, layout [c][o]             */
__device__ float g_b2p[H2];
__device__ float g_a2[H2];
__device__ float g_be2[H2];

__device__ __forceinline__ float sigm(float v) { return 1.f/(1.f+expf(-v)); }

/* ---------------- zero accumulators -------------------------------------- */
__global__ void k_zero() {
    int t = threadIdx.x;
    g_acc0[t]=0.f; g_accH[t]=0.f; g_accL[t]=0.f;
    g_sum1[t]=0.f; g_sq1[t]=0.f;
    if (t < H2) { g_sum2[t]=0.f; g_sq2[t]=0.f; }
}

/* ---------------- transpose W1 -> [k][o] --------------------------------- */
__global__ void k_tr(const float* __restrict__ W1) {
    int c = blockIdx.x, o = threadIdx.x;
    g_W1t[c*256 + o] = W1[o*512 + c];
}

/* ---------------- channel-mean accumulation (ECA stage 1) ---------------- */
__global__ void k_accum(const float* __restrict__ z0, const float* __restrict__ z1) {
    int b = blockIdx.x, c = threadIdx.x;
    float acc = 0.f;
    if (b < 50) {
        int r0 = b*30;
        #pragma unroll 6
        for (int i=0;i<30;i++) acc += z0[(r0+i)*D + c];
        atomicAdd(&g_acc0[c], acc);
    } else {
        int r0 = (b-50)*30;
        #pragma unroll 6
        for (int i=0;i<30;i++) acc += z1[(r0+i)*D + c];
        if (r0 < CATC) atomicAdd(&g_accH[c], acc);
        else           atomicAdd(&g_accL[c], acc);
    }
}

/* ---------------- small prep: s0, hm, lm, meanH (single block) ----------- */
__global__ void k_prep(const float* __restrict__ z1,
                       const float* __restrict__ w1, const float* __restrict__ w2,
                       const float* __restrict__ w3, const float* __restrict__ w4,
                       const float* __restrict__ w5,
                       const int* __restrict__ cdrH, const int* __restrict__ cdrL,
                       const int* __restrict__ notH, const int* __restrict__ notL,
                       int nHc, int nLc, int nHn, int nLn) {
    __shared__ float y0[D];
    __shared__ float av[W96];
    __shared__ float bv[CATC];
    __shared__ float red[256];
    int t = threadIdx.x;

    y0[t] = g_acc0[t] * (1.f/N0);
    __syncthreads();
    {
        float a = 0.f;
        #pragma unroll
        for (int k=0;k<5;k++) { int cc=t+k-2; if (cc>=0 && cc<D) a += w1[k]*y0[cc]; }
        g_s0[t] = sigm(a);
    }

    float sH0;
    {
        float yh0=g_accH[0]*(1.f/CATC), yh1=g_accH[1]*(1.f/CATC), yh2=g_accH[2]*(1.f/CATC);
        sH0 = sigm(w2[2]*yh0 + w2[3]*yh1 + w2[4]*yh2);
    }
    if (t < nHc) av[t] = z1[cdrH[t]*D] * sH0;
    for (int j=t; j<nHn; j+=256) bv[j] = z1[notH[j]*D] * sH0;
    __syncthreads();
    float msumH = 0.f;
    if (t < nHc) { float ai=av[t]; for (int j=0;j<nHn;j++) msumH += fabsf(ai - bv[j]); }
    red[t] = (t<nHc)? msumH : 0.f;
    __syncthreads();
    for (int m=128;m>0;m>>=1){ if(t<m) red[t]+=red[t+m]; __syncthreads(); }
    float gH = sigm(w4[2] * red[0] / ((float)nHc*(float)nHn));
    float myhm = (t<nHc) ? gH * msumH / (float)nHn : 0.f;
    if (t < nHc) g_t[t] = myhm;
    __syncthreads();

    float sL0;
    {
        float yl0=g_accL[0]*(1.f/CATC), yl1=g_accL[1]*(1.f/CATC), yl2=g_accL[2]*(1.f/CATC);
        sL0 = sigm(w3[2]*yl0 + w3[3]*yl1 + w3[4]*yl2);
    }
    if (t < nLc) av[t] = z1[(CATC+cdrL[t])*D] * sL0;
    for (int j=t; j<nLn; j+=256) bv[j] = z1[(CATC+notL[j])*D] * sL0;
    __syncthreads();
    float msumL = 0.f;
    if (t < nLc) { float ai=av[t]; for (int j=0;j<nLn;j++) msumL += fabsf(ai - bv[j]); }
    red[t] = (t<nLc)? msumL : 0.f;
    __syncthreads();
    for (int m=128;m>0;m>>=1){ if(t<m) red[t]+=red[t+m]; __syncthreads(); }
    float gL = sigm(w5[2] * red[0] / ((float)nLc*(float)nLn));
    if (t < nLc) g_t[nHc + t] = gL * msumL / (float)nLn;
    __syncthreads();

    red[t] = myhm;
    __syncthreads();
    for (int m=128;m>0;m>>=1){ if(t<m) red[t]+=red[t+m]; __syncthreads(); }
    if (t==0) g_meanH = red[0] / (float)nHc;
}

/* ---------------- per-h vectors x, m0, m1 and u = W1hi . x --------------- */
#define HB 10
__global__ __launch_bounds__(256) void k_pre2(const float* __restrict__ z0, int nHc) {
    __shared__ float xsall[HB][D];
    __shared__ float ts[W96];
    const int t = threadIdx.x;
    const int hbase = blockIdx.x * HB;
    if (t < W96) ts[t] = g_t[t];
    const float s0 = g_s0[t];
    const float mh = g_meanH;
    const float inv = 1.f / (float)nHc;
    __syncthreads();
    #pragma unroll
    for (int hh=0; hh<HB; hh++) {
        int h = hbase + hh;
        float x = z0[h*D + t] * s0;
        xsall[hh][t] = x;
        g_x [h*D + t] = x;
        float s = 0.f;
        for (int k=0;k<nHc;k++) s += fabsf(x - ts[k]);
        g_m0[h*D + t] = s * inv;
        g_m1[h*D + t] = x * mh;
    }
    __syncthreads();
    float u[HB];
    #pragma unroll
    for (int hh=0;hh<HB;hh++) u[hh]=0.f;
    for (int c=0;c<D;c++) {
        float wv = g_W1t[(256+c)*256 + t];
        #pragma unroll
        for (int hh=0;hh<HB;hh++) u[hh] = fmaf(wv, xsall[hh][c], u[hh]);
    }
    #pragma unroll
    for (int hh=0;hh<HB;hh++) g_u[(hbase+hh)*D + t] = u[hh];
}

/* ======================================================================== */
/* GEMM1-H : C[256, totH] over flattened (h,w<nHc) pixels. K=256.           */
/* block: 128 thr, tile 128(M) x 96(N), thread 8x12. Rank-1 u*hm + bias,    */
/* relu, store to g_c1, fused BN stats.                                     */
/* ======================================================================== */
__global__ __launch_bounds__(128,3) void k_g1a(const float* __restrict__ b1,
                                               int nHc, int totH) {
    const int tid = threadIdx.x;
    const int tm  = tid >> 3;     /* 0..15 : 8 outs   */
    const int tn  = tid & 7;      /* 0..7  : 12 cols  */
    const int ob  = blockIdx.y * 128;
    const int pb  = blockIdx.x * 96;

    __shared__ float As[32*128];
    __shared__ float Bs[32*96];
    __shared__ int   hrow[96];
    __shared__ int   pcol[96];
    __shared__ float tcol[96];

    if (tid < 96) {
        int pix = pb + tid;
        if (pix >= totH) pix = totH - 1;
        int h = pix / nHc, w = pix - h*nHc;
        hrow[tid] = h*D;
        pcol[tid] = h*W96 + w;
        tcol[tid] = g_t[w];
    }
    __syncthreads();

    float acc[8][12];
    #pragma unroll
    for (int i=0;i<8;i++)
        #pragma unroll
        for (int j=0;j<12;j++) acc[i][j]=0.f;

    for (int kc=0; kc<256; kc+=32) {
        #pragma unroll
        for (int r=0;r<8;r++) {
            int i4 = tid + r*128;               /* 1024 float4 */
            int ci = i4 >> 5, c4 = (i4 & 31) << 2;
            *(float4*)&As[ci*128 + c4] = *(const float4*)&g_W1t[(kc+ci)*256 + ob + c4];
        }
        #pragma unroll
        for (int r=0;r<24;r++) {
            int v = tid + r*128;                /* 3072 values */
            int ci = v / 96, n = v - ci*96;
            Bs[ci*96 + n] = fabsf(g_x[hrow[n] + kc + ci] - tcol[n]);
        }
        __syncthreads();
        #pragma unroll
        for (int ci=0;ci<32;ci++) {
            float4 a0 = *(const float4*)&As[ci*128 + tm*8];
            float4 a1 = *(const float4*)&As[ci*128 + tm*8 + 4];
            float4 c0 = *(const float4*)&Bs[ci*96 + tn*12];
            float4 c1 = *(const float4*)&Bs[ci*96 + tn*12 + 4];
            float4 c2 = *(const float4*)&Bs[ci*96 + tn*12 + 8];
            float av[8]  = {a0.x,a0.y,a0.z,a0.w,a1.x,a1.y,a1.z,a1.w};
            float bv[12] = {c0.x,c0.y,c0.z,c0.w,c1.x,c1.y,c1.z,c1.w,c2.x,c2.y,c2.z,c2.w};
            #pragma unroll
            for (int i=0;i<8;i++)
                #pragma unroll
                for (int j=0;j<12;j++)
                    acc[i][j] = fmaf(av[i], bv[j], acc[i][j]);
        }
        __syncthreads();
    }

    #pragma unroll
    for (int i=0;i<8;i++) {
        int o = ob + tm*8 + i;
        float bias = b1[o];
        float s = 0.f, q = 0.f;
        #pragma unroll
        for (int j=0;j<12;j++) {
            int n = tn*12 + j;
            float r = fmaxf(fmaf(g_u[hrow[n] + o], tcol[n], acc[i][j]) + bias, 0.f);
            if (pb + n < totH) {
                g_c1[(size_t)o*NPIX + pcol[n]] = r;
                s += r; q += r*r;
            }
        }
        #pragma unroll
        for (int off=4; off; off>>=1) {
            s += __shfl_down_sync(0xffffffffu, s, off, 8);
            q += __shfl_down_sync(0xffffffffu, q, off, 8);
        }
        if (tn == 0) { atomicAdd(&g_sum1[o], s); atomicAdd(&g_sq1[o], q); }
    }
}

/* ======================================================================== */
/* GEMM1-L : C[256, totL] over flattened (h,w<nLc) pixels. K=512 (m0|m1).   */
/* ======================================================================== */
__global__ __launch_bounds__(128,3) void k_g1b(const float* __restrict__ b1,
                                               int nHc, int nLc, int totL) {
    const int tid = threadIdx.x;
    const int tm  = tid >> 3;
    const int tn  = tid & 7;
    const int ob  = blockIdx.y * 128;
    const int pb  = blockIdx.x * 96;

    __shared__ float As[32*128];
    __shared__ float Bs[32*96];
    __shared__ int   hrow[96];
    __shared__ int   pcol[96];
    __shared__ float tcol[96];

    if (tid < 96) {
        int pix = pb + tid;
        if (pix >= totL) pix = totL - 1;
        int h = pix / nLc, w = pix - h*nLc;
        hrow[tid] = h*D;
        pcol[tid] = h*W96 + nHc + w;
        tcol[tid] = g_t[nHc + w];
    }
    __syncthreads();

    float acc[8][12];
    #pragma unroll
    for (int i=0;i<8;i++)
        #pragma unroll
        for (int j=0;j<12;j++) acc[i][j]=0.f;

    for (int kc=0; kc<512; kc+=32) {
        const float* src = (kc < 256) ? g_m0 : (g_m1 - 256);
        #pragma unroll
        for (int r=0;r<8;r++) {
            int i4 = tid + r*128;
            int ci = i4 >> 5, c4 = (i4 & 31) << 2;
            *(float4*)&As[ci*128 + c4] = *(const float4*)&g_W1t[(kc+ci)*256 + ob + c4];
        }
        #pragma unroll
        for (int r=0;r<24;r++) {
            int v = tid + r*128;
            int ci = v / 96, n = v - ci*96;
            Bs[ci*96 + n] = fabsf(src[hrow[n] + kc + ci] - tcol[n]);
        }
        __syncthreads();
        #pragma unroll
        for (int ci=0;ci<32;ci++) {
            float4 a0 = *(const float4*)&As[ci*128 + tm*8];
            float4 a1 = *(const float4*)&As[ci*128 + tm*8 + 4];
            float4 c0 = *(const float4*)&Bs[ci*96 + tn*12];
            float4 c1 = *(const float4*)&Bs[ci*96 + tn*12 + 4];
            float4 c2 = *(const float4*)&Bs[ci*96 + tn*12 + 8];
            float av[8]  = {a0.x,a0.y,a0.z,a0.w,a1.x,a1.y,a1.z,a1.w};
            float bv[12] = {c0.x,c0.y,c0.z,c0.w,c1.x,c1.y,c1.z,c1.w,c2.x,c2.y,c2.z,c2.w};
            #pragma unroll
            for (int i=0;i<8;i++)
                #pragma unroll
                for (int j=0;j<12;j++)
                    acc[i][j] = fmaf(av[i], bv[j], acc[i][j]);
        }
        __syncthreads();
    }

    #pragma unroll
    for (int i=0;i<8;i++) {
        int o = ob + tm*8 + i;
        float bias = b1[o];
        float s = 0.f, q = 0.f;
        #pragma unroll
        for (int j=0;j<12;j++) {
            int n = tn*12 + j;
            float r = fmaxf(acc[i][j] + bias, 0.f);
            if (pb + n < totL) {
                g_c1[(size_t)o*NPIX + pcol[n]] = r;
                s += r; q += r*r;
            }
        }
        #pragma unroll
        for (int off=4; off; off>>=1) {
            s += __shfl_down_sync(0xffffffffu, s, off, 8);
            q += __shfl_down_sync(0xffffffffu, q, off, 8);
        }
        if (tn == 0) { atomicAdd(&g_sum1[o], s); atomicAdd(&g_sq1[o], q); }
    }
}

/* ---------------- fold BN1 affine into W2 -------------------------------- */
__global__ void k_fold(const float* __restrict__ W2, const float* __restrict__ b2,
                       const float* __restrict__ g1, const float* __restrict__ bb1) {
    __shared__ float al[D], be[D];
    int t = threadIdx.x;
    float mean = g_sum1[t] * (1.f/NPIX);
    float var  = g_sq1[t]  * (1.f/NPIX) - mean*mean;
    float a    = g1[t] * rsqrtf(var + 1e-5f);
    al[t] = a; be[t] = bb1[t] - mean*a;
    __syncthreads();
    for (int v=t; v<H2*D; v+=256) {
        int o = v >> 8, c = v & 255;
        g_W2p[c*H2 + o] = W2[v] * al[c];
    }
    if (t < H2) {
        float s = b2[t];
        for (int c=0;c<D;c++) s += W2[t*D + c] * be[c];
        g_b2p[t] = s;
    }
}

/* ======================================================================== */
/* GEMM2 : M=128, K=256, N=144000, fused bias+relu+stats. 128x96 tiles.     */
/* ======================================================================== */
__global__ __launch_bounds__(128,3) void k_gemm2(float* __restrict__ out) {
    const int tid = threadIdx.x;
    const int tm  = tid >> 3;
    const int tn  = tid & 7;
    const int pb  = blockIdx.x * 96;

    __shared__ float As[32*128];
    __shared__ float Bs[32*96];

    float acc[8][12];
    #pragma unroll
    for (int i=0;i<8;i++)
        #pragma unroll
        for (int j=0;j<12;j++) acc[i][j]=0.f;

    for (int kc=0; kc<256; kc+=32) {
        #pragma unroll
        for (int r=0;r<8;r++) {
            int i4 = tid + r*128;               /* 1024 float4 */
            int ci = i4 >> 5, c4 = (i4 & 31) << 2;
            *(float4*)&As[ci*128 + c4] = *(const float4*)&g_W2p[(kc+ci)*H2 + c4];
        }
        #pragma unroll
        for (int r=0;r<6;r++) {
            int i4 = tid + r*128;               /* 768 float4 */
            int ci = i4 / 24, n4 = (i4 - ci*24) << 2;
            *(float4*)&Bs[ci*96 + n4] = *(const float4*)&g_c1[(size_t)(kc+ci)*NPIX + pb + n4];
        }
        __syncthreads();
        #pragma unroll
        for (int ci=0;ci<32;ci++) {
            float4 a0 = *(const float4*)&As[ci*128 + tm*8];
            float4 a1 = *(const float4*)&As[ci*128 + tm*8 + 4];
            float4 c0 = *(const float4*)&Bs[ci*96 + tn*12];
            float4 c1 = *(const float4*)&Bs[ci*96 + tn*12 + 4];
            float4 c2 = *(const float4*)&Bs[ci*96 + tn*12 + 8];
            float av[8]  = {a0.x,a0.y,a0.z,a0.w,a1.x,a1.y,a1.z,a1.w};
            float bv[12] = {c0.x,c0.y,c0.z,c0.w,c1.x,c1.y,c1.z,c1.w,c2.x,c2.y,c2.z,c2.w};
            #pragma unroll
            for (int i=0;i<8;i++)
                #pragma unroll
                for (int j=0;j<12;j++)
                    acc[i][j] = fmaf(av[i], bv[j], acc[i][j]);
        }
        __syncthreads();
    }

    #pragma unroll
    for (int i=0;i<8;i++) {
        int o = tm*8 + i;
        float bias = g_b2p[o];
        float s = 0.f, q = 0.f;
        #pragma unroll
        for (int j=0;j<12;j++) {
            float r = fmaxf(acc[i][j] + bias, 0.f);
            out[(size_t)o*NPIX + pb + tn*12 + j] = r;
            s += r; q += r*r;
        }
        #pragma unroll
        for (int off=4; off; off>>=1) {
            s += __shfl_down_sync(0xffffffffu, s, off, 8);
            q += __shfl_down_sync(0xffffffffu, q, off, 8);
        }
        if (tn == 0) { atomicAdd(&g_sum2[o], s); atomicAdd(&g_sq2[o], q); }
    }
}

__global__ void k_ab2(const float* __restrict__ g2, const float* __restrict__ bb2) {
    int t = threadIdx.x;
    float mean = g_sum2[t]*(1.f/NPIX);
    float var  = g_sq2[t]*(1.f/NPIX) - mean*mean;
    float a    = g2[t]*rsqrtf(var + 1e-5f);
    g_a2[t] = a; g_be2[t] = bb2[t] - mean*a;
}

/* ---------------- final BN2 affine in place ------------------------------ */
__global__ void k_final(float* __restrict__ out) {
    size_t idx = (size_t)blockIdx.x*256 + threadIdx.x;
    size_t i4  = idx * 4;
    int c = (int)(i4 / NPIX);
    float a = g_a2[c], b = g_be2[c];
    float4 v = *(float4*)(out + i4);
    v.x = fmaf(a, v.x, b); v.y = fmaf(a, v.y, b);
    v.z = fmaf(a, v.z, b); v.w = fmaf(a, v.w, b);
    *(float4*)(out + i4) = v;
}

/* ---------------- launch ------------------------------------------------- */
extern "C" void kernel_launch(void* const* d_in, const int* in_sizes, int n_in,
                              void* d_out, int out_size) {
    const float* z0  = (const float*)d_in[0];
    const float* z1  = (const float*)d_in[1];
    const float* w1  = (const float*)d_in[2];
    const float* w2  = (const float*)d_in[3];
    const float* w3  = (const float*)d_in[4];
    const float* w4  = (const float*)d_in[5];
    const float* w5  = (const float*)d_in[6];
    const float* W1  = (const float*)d_in[7];
    const float* b1  = (const float*)d_in[8];
    const float* g1  = (const float*)d_in[9];
    const float* bb1 = (const float*)d_in[10];
    const float* W2  = (const float*)d_in[11];
    const float* b2  = (const float*)d_in[12];
    const float* g2  = (const float*)d_in[13];
    const float* bb2 = (const float*)d_in[14];
    const int* cdrH = (const int*)d_in[16];
    const int* cdrL = (const int*)d_in[17];
    const int* notH = (const int*)d_in[18];
    const int* notL = (const int*)d_in[19];
    int nHc = in_sizes[16], nLc = in_sizes[17];
    int nHn = in_sizes[18], nLn = in_sizes[19];
    float* out = (float*)d_out;

    k_zero  <<<1, 256>>>();
    k_tr    <<<512, 256>>>(W1);
    k_accum <<<90, 256>>>(z0, z1);
    k_prep  <<<1, 256>>>(z1, w1, w2, w3, w4, w5, cdrH, cdrL, notH, notL,
                         nHc, nLc, nHn, nLn);
    k_pre2  <<<N0/HB, 256>>>(z0, nHc);

    int totH = N0 * nHc;
    int totL = N0 * nLc;
    if (nHc > 0) {
        dim3 gA((totH + 95) / 96, 2);
        k_g1a <<<gA, 128>>>(b1, nHc, totH);
    }
    if (nLc > 0) {
        dim3 gB((totL + 95) / 96, 2);
        k_g1b <<<gB, 128>>>(b1, nHc, nLc, totL);
    }
    k_fold  <<<1, 256>>>(W2, b2, g1, bb1);
    k_gemm2 <<<NPIX/96, 128>>>(out);
    k_ab2   <<<1, 128>>>(g2, bb2);
    k_final <<<18000, 256>>>(out);
}

// round 4
// speedup vs baseline: 3.0816x; 2.5547x over previous
#include <cuda_runtime.h>
#include <math.h>

#define D     256
#define N0    1500
#define N1    1200
#define CATC  600
#define W96   96
#define NPIX  (N0*W96)      /* 144000 */
#define HID   256
#define H2    128

/* ---------------- device scratch ----------------------------------------- */
__device__ float    g_s0[D];
__device__ float    g_acc0[D];
__device__ float    g_accH[D];
__device__ float    g_accL[D];
__device__ float    g_t[W96];
__device__ float    g_meanH;
__device__ float    g_W1t[512*256];     /* W1 [k][o] fp32 (for u-gemm)      */
__device__ unsigned g_W1tf[256*512];    /* W1 [o][k] tf32 bits              */
__device__ float    g_x [N0*D];
__device__ float    g_m0[N0*D];
__device__ float    g_m1[N0*D];
__device__ float    g_u [N0*D];
__device__ float    g_c1[(size_t)HID*NPIX];
__device__ float    g_sum1[HID];
__device__ float    g_sq1[HID];
__device__ float    g_sum2[H2];
__device__ float    g_sq2[H2];
__device__ unsigned g_W2p[H2*D];        /* folded W2 [o][c] tf32 bits       */
__device__ float    g_b2p[H2];
__device__ float    g_a2[H2];
__device__ float    g_be2[H2];

__device__ __forceinline__ float sigm(float v) { return 1.f/(1.f+expf(-v)); }
__device__ __forceinline__ unsigned f2tf(float f) {
    unsigned u; asm("cvt.rna.tf32.f32 %0, %1;" : "=r"(u) : "f"(f)); return u;
}
__device__ __forceinline__ void mma8(float c[4], unsigned a0, unsigned a1,
                                     unsigned a2, unsigned a3,
                                     unsigned b0, unsigned b1) {
    asm("mma.sync.aligned.m16n8k8.row.col.f32.tf32.tf32.f32 "
        "{%0,%1,%2,%3},{%4,%5,%6,%7},{%8,%9},{%0,%1,%2,%3};"
        : "+f"(c[0]),"+f"(c[1]),"+f"(c[2]),"+f"(c[3])
        : "r"(a0),"r"(a1),"r"(a2),"r"(a3),"r"(b0),"r"(b1));
}

/* ---------------- zero accumulators -------------------------------------- */
__global__ void k_zero() {
    int t = threadIdx.x;
    g_acc0[t]=0.f; g_accH[t]=0.f; g_accL[t]=0.f;
    g_sum1[t]=0.f; g_sq1[t]=0.f;
    if (t < H2) { g_sum2[t]=0.f; g_sq2[t]=0.f; }
}

/* ---------------- W1 transposes / conversions ----------------------------- */
__global__ void k_tr(const float* __restrict__ W1) {
    int c = blockIdx.x, o = threadIdx.x;
    g_W1t[c*256 + o] = W1[o*512 + c];
}
__global__ void k_tr2(const float* __restrict__ W1) {
    int o = blockIdx.x, c = threadIdx.x;      /* 512 threads */
    g_W1tf[o*512 + c] = f2tf(W1[o*512 + c]);
}

/* ---------------- channel-mean accumulation ------------------------------- */
__global__ void k_accum(const float* __restrict__ z0, const float* __restrict__ z1) {
    int b = blockIdx.x, c = threadIdx.x;
    float acc = 0.f;
    if (b < 50) {
        int r0 = b*30;
        #pragma unroll 6
        for (int i=0;i<30;i++) acc += z0[(r0+i)*D + c];
        atomicAdd(&g_acc0[c], acc);
    } else {
        int r0 = (b-50)*30;
        #pragma unroll 6
        for (int i=0;i<30;i++) acc += z1[(r0+i)*D + c];
        if (r0 < CATC) atomicAdd(&g_accH[c], acc);
        else           atomicAdd(&g_accL[c], acc);
    }
}

/* ---------------- small prep: s0, hm, lm, meanH --------------------------- */
__global__ void k_prep(const float* __restrict__ z1,
                       const float* __restrict__ w1, const float* __restrict__ w2,
                       const float* __restrict__ w3, const float* __restrict__ w4,
                       const float* __restrict__ w5,
                       const int* __restrict__ cdrH, const int* __restrict__ cdrL,
                       const int* __restrict__ notH, const int* __restrict__ notL,
                       int nHc, int nLc, int nHn, int nLn) {
    __shared__ float y0[D];
    __shared__ float av[W96];
    __shared__ float bv[CATC];
    __shared__ float red[256];
    int t = threadIdx.x;

    y0[t] = g_acc0[t] * (1.f/N0);
    __syncthreads();
    {
        float a = 0.f;
        #pragma unroll
        for (int k=0;k<5;k++) { int cc=t+k-2; if (cc>=0 && cc<D) a += w1[k]*y0[cc]; }
        g_s0[t] = sigm(a);
    }

    float sH0;
    {
        float yh0=g_accH[0]*(1.f/CATC), yh1=g_accH[1]*(1.f/CATC), yh2=g_accH[2]*(1.f/CATC);
        sH0 = sigm(w2[2]*yh0 + w2[3]*yh1 + w2[4]*yh2);
    }
    if (t < nHc) av[t] = z1[cdrH[t]*D] * sH0;
    for (int j=t; j<nHn; j+=256) bv[j] = z1[notH[j]*D] * sH0;
    __syncthreads();
    float msumH = 0.f;
    if (t < nHc) { float ai=av[t]; for (int j=0;j<nHn;j++) msumH += fabsf(ai - bv[j]); }
    red[t] = (t<nHc)? msumH : 0.f;
    __syncthreads();
    for (int m=128;m>0;m>>=1){ if(t<m) red[t]+=red[t+m]; __syncthreads(); }
    float gH = sigm(w4[2] * red[0] / ((float)nHc*(float)nHn));
    float myhm = (t<nHc) ? gH * msumH / (float)nHn : 0.f;
    if (t < nHc) g_t[t] = myhm;
    __syncthreads();

    float sL0;
    {
        float yl0=g_accL[0]*(1.f/CATC), yl1=g_accL[1]*(1.f/CATC), yl2=g_accL[2]*(1.f/CATC);
        sL0 = sigm(w3[2]*yl0 + w3[3]*yl1 + w3[4]*yl2);
    }
    if (t < nLc) av[t] = z1[(CATC+cdrL[t])*D] * sL0;
    for (int j=t; j<nLn; j+=256) bv[j] = z1[(CATC+notL[j])*D] * sL0;
    __syncthreads();
    float msumL = 0.f;
    if (t < nLc) { float ai=av[t]; for (int j=0;j<nLn;j++) msumL += fabsf(ai - bv[j]); }
    red[t] = (t<nLc)? msumL : 0.f;
    __syncthreads();
    for (int m=128;m>0;m>>=1){ if(t<m) red[t]+=red[t+m]; __syncthreads(); }
    float gL = sigm(w5[2] * red[0] / ((float)nLc*(float)nLn));
    if (t < nLc) g_t[nHc + t] = gL * msumL / (float)nLn;
    __syncthreads();

    red[t] = myhm;
    __syncthreads();
    for (int m=128;m>0;m>>=1){ if(t<m) red[t]+=red[t+m]; __syncthreads(); }
    if (t==0) g_meanH = red[0] / (float)nHc;
}

/* ---------------- per-h vectors x, m0, m1 and u = W1hi . x ---------------- */
#define HB 10
__global__ __launch_bounds__(256) void k_pre2(const float* __restrict__ z0, int nHc) {
    __shared__ float xsall[HB][D];
    __shared__ float ts[W96];
    const int t = threadIdx.x;
    const int hbase = blockIdx.x * HB;
    if (t < W96) ts[t] = g_t[t];
    const float s0 = g_s0[t];
    const float mh = g_meanH;
    const float inv = 1.f / (float)nHc;
    __syncthreads();
    #pragma unroll
    for (int hh=0; hh<HB; hh++) {
        int h = hbase + hh;
        float x = z0[h*D + t] * s0;
        xsall[hh][t] = x;
        g_x [h*D + t] = x;
        float s = 0.f;
        for (int k=0;k<nHc;k++) s += fabsf(x - ts[k]);
        g_m0[h*D + t] = s * inv;
        g_m1[h*D + t] = x * mh;
    }
    __syncthreads();
    float u[HB];
    #pragma unroll
    for (int hh=0;hh<HB;hh++) u[hh]=0.f;
    for (int c=0;c<D;c++) {
        float wv = g_W1t[(256+c)*256 + t];
        #pragma unroll
        for (int hh=0;hh<HB;hh++) u[hh] = fmaf(wv, xsall[hh][c], u[hh]);
    }
    #pragma unroll
    for (int hh=0;hh<HB;hh++) g_u[(hbase+hh)*D + t] = u[hh];
}

/* ======================================================================== */
/* Tensor-core GEMM1 (H and L variants). 256 thr, tile 128x128, KC=32.      */
/* warps 2(M) x 4(N); warp tile 64x32 = 4x4 m16n8k8 frags.                  */
/* ======================================================================== */
#define SPAD 36

__global__ __launch_bounds__(256,2) void k_g1a(const float* __restrict__ b1,
                                               int nHc, int totH) {
    const int tid = threadIdx.x;
    const int wid = tid >> 5, lane = tid & 31;
    const int wm = wid >> 2, wn = wid & 3;
    const int g = lane >> 2, tig = lane & 3;
    const int ob = blockIdx.y * 128;
    const int pb = blockIdx.x * 128;

    __shared__ unsigned As[128*SPAD];
    __shared__ unsigned Bs[128*SPAD];
    __shared__ int   hrow[128];
    __shared__ int   pcol[128];
    __shared__ float tcol[128];

    if (tid < 128) {
        int pix = pb + tid;
        if (pix >= totH) pix = totH - 1;
        int h = pix / nHc, w = pix - h*nHc;
        hrow[tid] = h*D;
        pcol[tid] = h*W96 + w;
        tcol[tid] = g_t[w];
    }
    __syncthreads();

    float c[4][4][4];
    #pragma unroll
    for (int i=0;i<4;i++) for (int j=0;j<4;j++) for (int k=0;k<4;k++) c[i][j][k]=0.f;

    const int sm = tid >> 1;               /* staging row 0..127 */
    const int sk = (tid & 1) * 16;         /* staging k  0 or 16 */
    const int hb = hrow[sm];
    const float tv = tcol[sm];

    for (int kc=0; kc<256; kc+=32) {
        #pragma unroll
        for (int q=0;q<4;q++) {
            uint4 a = *(const uint4*)&g_W1tf[(ob+sm)*512 + kc + sk + q*4];
            *(uint4*)&As[sm*SPAD + sk + q*4] = a;
        }
        #pragma unroll
        for (int q=0;q<4;q++) {
            float4 xv = *(const float4*)&g_x[hb + kc + sk + q*4];
            uint4 o;
            o.x = f2tf(fabsf(xv.x - tv)); o.y = f2tf(fabsf(xv.y - tv));
            o.z = f2tf(fabsf(xv.z - tv)); o.w = f2tf(fabsf(xv.w - tv));
            *(uint4*)&Bs[sm*SPAD + sk + q*4] = o;
        }
        __syncthreads();
        #pragma unroll
        for (int ks=0; ks<4; ks++) {
            const int kk = ks*8;
            unsigned af[4][4], bf[4][2];
            #pragma unroll
            for (int mt=0;mt<4;mt++) {
                int rb = (wm*64 + mt*16 + g)*SPAD + kk + tig;
                af[mt][0]=As[rb]; af[mt][1]=As[rb+8*SPAD];
                af[mt][2]=As[rb+4]; af[mt][3]=As[rb+8*SPAD+4];
            }
            #pragma unroll
            for (int nt=0;nt<4;nt++) {
                int cb = (wn*32 + nt*8 + g)*SPAD + kk + tig;
                bf[nt][0]=Bs[cb]; bf[nt][1]=Bs[cb+4];
            }
            #pragma unroll
            for (int mt=0;mt<4;mt++)
                #pragma unroll
                for (int nt=0;nt<4;nt++)
                    mma8(c[mt][nt], af[mt][0],af[mt][1],af[mt][2],af[mt][3],
                         bf[nt][0], bf[nt][1]);
        }
        __syncthreads();
    }

    /* epilogue: + u*t + bias, relu, store, stats */
    #pragma unroll
    for (int mt=0;mt<4;mt++) {
        #pragma unroll
        for (int half=0; half<2; half++) {
            int o = ob + wm*64 + mt*16 + g + half*8;
            float bias = b1[o];
            float s = 0.f, q = 0.f;
            #pragma unroll
            for (int nt=0;nt<4;nt++) {
                #pragma unroll
                for (int cc=0;cc<2;cc++) {
                    int n = wn*32 + nt*8 + tig*2 + cc;
                    float r = c[mt][nt][half*2+cc]
                            + g_u[hrow[n] + o] * tcol[n] + bias;
                    r = fmaxf(r, 0.f);
                    if (pb + n < totH) {
                        g_c1[(size_t)o*NPIX + pcol[n]] = r;
                        s += r; q += r*r;
                    }
                }
            }
            s += __shfl_down_sync(0xffffffffu, s, 2, 4);
            s += __shfl_down_sync(0xffffffffu, s, 1, 4);
            q += __shfl_down_sync(0xffffffffu, q, 2, 4);
            q += __shfl_down_sync(0xffffffffu, q, 1, 4);
            if (tig == 0) { atomicAdd(&g_sum1[o], s); atomicAdd(&g_sq1[o], q); }
        }
    }
}

__global__ __launch_bounds__(256,2) void k_g1b(const float* __restrict__ b1,
                                               int nHc, int nLc, int totL) {
    const int tid = threadIdx.x;
    const int wid = tid >> 5, lane = tid & 31;
    const int wm = wid >> 2, wn = wid & 3;
    const int g = lane >> 2, tig = lane & 3;
    const int ob = blockIdx.y * 128;
    const int pb = blockIdx.x * 128;

    __shared__ unsigned As[128*SPAD];
    __shared__ unsigned Bs[128*SPAD];
    __shared__ int   hrow[128];
    __shared__ int   pcol[128];
    __shared__ float tcol[128];

    if (tid < 128) {
        int pix = pb + tid;
        if (pix >= totL) pix = totL - 1;
        int h = pix / nLc, w = pix - h*nLc;
        hrow[tid] = h*D;
        pcol[tid] = h*W96 + nHc + w;
        tcol[tid] = g_t[nHc + w];
    }
    __syncthreads();

    float c[4][4][4];
    #pragma unroll
    for (int i=0;i<4;i++) for (int j=0;j<4;j++) for (int k=0;k<4;k++) c[i][j][k]=0.f;

    const int sm = tid >> 1;
    const int sk = (tid & 1) * 16;
    const int hb = hrow[sm];
    const float tv = tcol[sm];

    for (int kc=0; kc<512; kc+=32) {
        const float* src = (kc < 256) ? g_m0 : g_m1;
        const int kcl = kc & 255;
        #pragma unroll
        for (int q=0;q<4;q++) {
            uint4 a = *(const uint4*)&g_W1tf[(ob+sm)*512 + kc + sk + q*4];
            *(uint4*)&As[sm*SPAD + sk + q*4] = a;
        }
        #pragma unroll
        for (int q=0;q<4;q++) {
            float4 xv = *(const float4*)&src[hb + kcl + sk + q*4];
            uint4 o;
            o.x = f2tf(fabsf(xv.x - tv)); o.y = f2tf(fabsf(xv.y - tv));
            o.z = f2tf(fabsf(xv.z - tv)); o.w = f2tf(fabsf(xv.w - tv));
            *(uint4*)&Bs[sm*SPAD + sk + q*4] = o;
        }
        __syncthreads();
        #pragma unroll
        for (int ks=0; ks<4; ks++) {
            const int kk = ks*8;
            unsigned af[4][4], bf[4][2];
            #pragma unroll
            for (int mt=0;mt<4;mt++) {
                int rb = (wm*64 + mt*16 + g)*SPAD + kk + tig;
                af[mt][0]=As[rb]; af[mt][1]=As[rb+8*SPAD];
                af[mt][2]=As[rb+4]; af[mt][3]=As[rb+8*SPAD+4];
            }
            #pragma unroll
            for (int nt=0;nt<4;nt++) {
                int cb = (wn*32 + nt*8 + g)*SPAD + kk + tig;
                bf[nt][0]=Bs[cb]; bf[nt][1]=Bs[cb+4];
            }
            #pragma unroll
            for (int mt=0;mt<4;mt++)
                #pragma unroll
                for (int nt=0;nt<4;nt++)
                    mma8(c[mt][nt], af[mt][0],af[mt][1],af[mt][2],af[mt][3],
                         bf[nt][0], bf[nt][1]);
        }
        __syncthreads();
    }

    #pragma unroll
    for (int mt=0;mt<4;mt++) {
        #pragma unroll
        for (int half=0; half<2; half++) {
            int o = ob + wm*64 + mt*16 + g + half*8;
            float bias = b1[o];
            float s = 0.f, q = 0.f;
            #pragma unroll
            for (int nt=0;nt<4;nt++) {
                #pragma unroll
                for (int cc=0;cc<2;cc++) {
                    int n = wn*32 + nt*8 + tig*2 + cc;
                    float r = fmaxf(c[mt][nt][half*2+cc] + bias, 0.f);
                    if (pb + n < totL) {
                        g_c1[(size_t)o*NPIX + pcol[n]] = r;
                        s += r; q += r*r;
                    }
                }
            }
            s += __shfl_down_sync(0xffffffffu, s, 2, 4);
            s += __shfl_down_sync(0xffffffffu, s, 1, 4);
            q += __shfl_down_sync(0xffffffffu, q, 2, 4);
            q += __shfl_down_sync(0xffffffffu, q, 1, 4);
            if (tig == 0) { atomicAdd(&g_sum1[o], s); atomicAdd(&g_sq1[o], q); }
        }
    }
}

/* ---------------- fold BN1 affine into W2 (tf32) -------------------------- */
__global__ void k_fold(const float* __restrict__ W2, const float* __restrict__ b2,
                       const float* __restrict__ g1, const float* __restrict__ bb1) {
    __shared__ float al[D], be[D];
    int t = threadIdx.x;
    float mean = g_sum1[t] * (1.f/NPIX);
    float var  = g_sq1[t]  * (1.f/NPIX) - mean*mean;
    float a    = g1[t] * rsqrtf(var + 1e-5f);
    al[t] = a; be[t] = bb1[t] - mean*a;
    __syncthreads();
    for (int v=t; v<H2*D; v+=256) {
        int c = v & 255;
        g_W2p[v] = f2tf(W2[v] * al[c]);
    }
    if (t < H2) {
        float s = b2[t];
        for (int c=0;c<D;c++) s += W2[t*D + c] * be[c];
        g_b2p[t] = s;
    }
}

/* ======================================================================== */
/* Tensor-core GEMM2 : M=128, K=256, N=144000                               */
/* ======================================================================== */
__global__ __launch_bounds__(256,2) void k_gemm2(float* __restrict__ out) {
    const int tid = threadIdx.x;
    const int wid = tid >> 5, lane = tid & 31;
    const int wm = wid >> 2, wn = wid & 3;
    const int g = lane >> 2, tig = lane & 3;
    const int pb = blockIdx.x * 128;

    __shared__ unsigned As[128*SPAD];
    __shared__ unsigned Bs[128*SPAD];

    float c[4][4][4];
    #pragma unroll
    for (int i=0;i<4;i++) for (int j=0;j<4;j++) for (int k=0;k<4;k++) c[i][j][k]=0.f;

    const int sm = tid >> 1;
    const int sk = (tid & 1) * 16;

    for (int kc=0; kc<256; kc+=32) {
        /* A: g_W2p [o][256], rows 0..127 */
        {
            uint4 a0 = *(const uint4*)&g_W2p[sm*256 + kc + sk];
            uint4 a1 = *(const uint4*)&g_W2p[sm*256 + kc + sk + 4];
            uint4 a2 = *(const uint4*)&g_W2p[sm*256 + kc + sk + 8];
            uint4 a3 = *(const uint4*)&g_W2p[sm*256 + kc + sk + 12];
            *(uint4*)&As[sm*SPAD + sk     ] = a0;
            *(uint4*)&As[sm*SPAD + sk + 4 ] = a1;
            *(uint4*)&As[sm*SPAD + sk + 8 ] = a2;
            *(uint4*)&As[sm*SPAD + sk + 12] = a3;
        }
        /* B: g_c1 [k][pix] -> Bs n-major ; thread = (n=sm, k=sk..sk+15) */
        {
            unsigned bb[16];
            #pragma unroll
            for (int j=0;j<16;j++)
                bb[j] = f2tf(g_c1[(size_t)(kc + sk + j)*NPIX + pb + sm]);
            #pragma unroll
            for (int q=0;q<4;q++)
                *(uint4*)&Bs[sm*SPAD + sk + q*4] =
                    make_uint4(bb[q*4], bb[q*4+1], bb[q*4+2], bb[q*4+3]);
        }
        __syncthreads();
        #pragma unroll
        for (int ks=0; ks<4; ks++) {
            const int kk = ks*8;
            unsigned af[4][4], bf[4][2];
            #pragma unroll
            for (int mt=0;mt<4;mt++) {
                int rb = (wm*64 + mt*16 + g)*SPAD + kk + tig;
                af[mt][0]=As[rb]; af[mt][1]=As[rb+8*SPAD];
                af[mt][2]=As[rb+4]; af[mt][3]=As[rb+8*SPAD+4];
            }
            #pragma unroll
            for (int nt=0;nt<4;nt++) {
                int cb = (wn*32 + nt*8 + g)*SPAD + kk + tig;
                bf[nt][0]=Bs[cb]; bf[nt][1]=Bs[cb+4];
            }
            #pragma unroll
            for (int mt=0;mt<4;mt++)
                #pragma unroll
                for (int nt=0;nt<4;nt++)
                    mma8(c[mt][nt], af[mt][0],af[mt][1],af[mt][2],af[mt][3],
                         bf[nt][0], bf[nt][1]);
        }
        __syncthreads();
    }

    #pragma unroll
    for (int mt=0;mt<4;mt++) {
        #pragma unroll
        for (int half=0; half<2; half++) {
            int o = wm*64 + mt*16 + g + half*8;
            float bias = g_b2p[o];
            float s = 0.f, q = 0.f;
            #pragma unroll
            for (int nt=0;nt<4;nt++) {
                int n = pb + wn*32 + nt*8 + tig*2;
                float r0 = fmaxf(c[mt][nt][half*2+0] + bias, 0.f);
                float r1 = fmaxf(c[mt][nt][half*2+1] + bias, 0.f);
                *(float2*)&out[(size_t)o*NPIX + n] = make_float2(r0, r1);
                s += r0 + r1; q += r0*r0 + r1*r1;
            }
            s += __shfl_down_sync(0xffffffffu, s, 2, 4);
            s += __shfl_down_sync(0xffffffffu, s, 1, 4);
            q += __shfl_down_sync(0xffffffffu, q, 2, 4);
            q += __shfl_down_sync(0xffffffffu, q, 1, 4);
            if (tig == 0) { atomicAdd(&g_sum2[o], s); atomicAdd(&g_sq2[o], q); }
        }
    }
}

__global__ void k_ab2(const float* __restrict__ g2, const float* __restrict__ bb2) {
    int t = threadIdx.x;
    float mean = g_sum2[t]*(1.f/NPIX);
    float var  = g_sq2[t]*(1.f/NPIX) - mean*mean;
    float a    = g2[t]*rsqrtf(var + 1e-5f);
    g_a2[t] = a; g_be2[t] = bb2[t] - mean*a;
}

/* ---------------- final BN2 affine in place ------------------------------- */
__global__ void k_final(float* __restrict__ out) {
    size_t idx = (size_t)blockIdx.x*256 + threadIdx.x;
    size_t i4  = idx * 4;
    int c = (int)(i4 / NPIX);
    float a = g_a2[c], b = g_be2[c];
    float4 v = *(float4*)(out + i4);
    v.x = fmaf(a, v.x, b); v.y = fmaf(a, v.y, b);
    v.z = fmaf(a, v.z, b); v.w = fmaf(a, v.w, b);
    *(float4*)(out + i4) = v;
}

/* ---------------- launch -------------------------------------------------- */
extern "C" void kernel_launch(void* const* d_in, const int* in_sizes, int n_in,
                              void* d_out, int out_size) {
    const float* z0  = (const float*)d_in[0];
    const float* z1  = (const float*)d_in[1];
    const float* w1  = (const float*)d_in[2];
    const float* w2  = (const float*)d_in[3];
    const float* w3  = (const float*)d_in[4];
    const float* w4  = (const float*)d_in[5];
    const float* w5  = (const float*)d_in[6];
    const float* W1  = (const float*)d_in[7];
    const float* b1  = (const float*)d_in[8];
    const float* g1  = (const float*)d_in[9];
    const float* bb1 = (const float*)d_in[10];
    const float* W2  = (const float*)d_in[11];
    const float* b2  = (const float*)d_in[12];
    const float* g2  = (const float*)d_in[13];
    const float* bb2 = (const float*)d_in[14];
    const int* cdrH = (const int*)d_in[16];
    const int* cdrL = (const int*)d_in[17];
    const int* notH = (const int*)d_in[18];
    const int* notL = (const int*)d_in[19];
    int nHc = in_sizes[16], nLc = in_sizes[17];
    int nHn = in_sizes[18], nLn = in_sizes[19];
    float* out = (float*)d_out;

    k_zero  <<<1, 256>>>();
    k_tr    <<<512, 256>>>(W1);
    k_tr2   <<<256, 512>>>(W1);
    k_accum <<<90, 256>>>(z0, z1);
    k_prep  <<<1, 256>>>(z1, w1, w2, w3, w4, w5, cdrH, cdrL, notH, notL,
                         nHc, nLc, nHn, nLn);
    k_pre2  <<<N0/HB, 256>>>(z0, nHc);

    int totH = N0 * nHc;
    int totL = N0 * nLc;
    if (nHc > 0) {
        dim3 gA((totH + 127) / 128, 2);
        k_g1a <<<gA, 256>>>(b1, nHc, totH);
    }
    if (nLc > 0) {
        dim3 gB((totL + 127) / 128, 2);
        k_g1b <<<gB, 256>>>(b1, nHc, nLc, totL);
    }
    k_fold  <<<1, 256>>>(W2, b2, g1, bb1);
    k_gemm2 <<<NPIX/128, 256>>>(out);
    k_ab2   <<<1, 128>>>(g2, bb2);
    k_final <<<18000, 256>>>(out);
}